// round 14
// baseline (speedup 1.0000x reference)
#include <cuda_runtime.h>
#include <cuda_fp16.h>
#include <cstdint>

// ===========================================================================
// Problem constants
// ===========================================================================
namespace {
constexpr int B   = 4;
constexpr int S   = 1024;
constexpr int H   = 32;
constexpr int HKV = 8;
constexpr int D   = 128;

constexpr int BLK_E4 = 128 * HKV * D / 4;  // float4 per cache block group
constexpr int NCACHE = 64;                 // total cache blocks

// SCALE * log2(e): softmax computed in base-2 domain
constexpr float SCALE2 = 0.08838834764831845f * 1.4426950408889634f;
constexpr float LOG2E  = 1.4426950408889634f;

constexpr int BR = 64;    // q rows per CTA (4 warps x 16)
constexpr int BC = 64;    // kv cols per tile

// smem tiles, paired-fragment layout: one 16B unit = B-fragments of two
// consecutive k-steps. Row strides == 64 mod 128 bytes: conflict-free LDS.128.
// K: 64 rows x 256B data, stride 320B ; V: 128 rows x 128B data, stride 192B
constexpr uint32_t RS_K = 320;
constexpr uint32_t RS_V = 192;
constexpr uint32_t BUF_K = 0;
constexpr uint32_t BUF_V = 64 * RS_K;            // 20480
constexpr uint32_t BUF_SZ = BUF_V + 128 * RS_V;  // 45056
constexpr uint32_t SMEM_ATTN = 2 * BUF_SZ;       // 90112 (x2 CTAs = 176KB/SM)

// prep kernel job block ranges
constexpr int NB_COPY = NCACHE * 128;         // 8192 (copy, skip-overwritten)
constexpr int NB_CK   = (B * HKV * S) / 4;    // 8192 (4 K-rows per block)
constexpr int NB_CV   = B * HKV * (S / 64);   // 512
}  // namespace

// pre-converted fp16 scratch (8 MB each)
__device__ __align__(256) uint4 g_K[(size_t)B * HKV * S * 256 / 16];
__device__ __align__(256) uint4 g_V[(size_t)B * HKV * D * 2048 / 16];

// ===========================================================================
// helpers
// ===========================================================================
static __device__ __forceinline__ void mma16816(float* c, uint32_t a0,
                                                uint32_t a1, uint32_t a2,
                                                uint32_t a3, uint32_t b0,
                                                uint32_t b1) {
    asm volatile(
        "mma.sync.aligned.m16n8k16.row.col.f32.f16.f16.f32 "
        "{%0,%1,%2,%3}, {%4,%5,%6,%7}, {%8,%9}, {%0,%1,%2,%3};"
        : "+f"(c[0]), "+f"(c[1]), "+f"(c[2]), "+f"(c[3])
        : "r"(a0), "r"(a1), "r"(a2), "r"(a3), "r"(b0), "r"(b1));
}

static __device__ __forceinline__ uint32_t pkh(float x, float y) {
    __half2 t = __floats2half2_rn(x, y);
    return *reinterpret_cast<uint32_t*>(&t);
}

static __device__ __forceinline__ uint32_t s2u(const void* p) {
    uint32_t a;
    asm("{ .reg .u64 t; cvta.to.shared.u64 t, %1; cvt.u32.u64 %0, t; }"
        : "=r"(a) : "l"(p));
    return a;
}

static __device__ __forceinline__ void cpa16(uint32_t dst, const void* src) {
    asm volatile("cp.async.cg.shared.global [%0], [%1], 16;"
                 :: "r"(dst), "l"(src));
}
#define CP_COMMIT() asm volatile("cp.async.commit_group;" ::: "memory")
#define CP_WAIT(n) asm volatile("cp.async.wait_group %0;" :: "n"(n) : "memory")

// ===========================================================================
// Fused prep kernel: copy (skip-overwritten) + scatter + convert K + convert V
// (unchanged from R13 — layouts identical)
// ===========================================================================
__global__ void prep_kernel(const float4* __restrict__ k,
                            const float4* __restrict__ v,
                            const float4* __restrict__ kc_in,
                            const float4* __restrict__ vc_in,
                            const int* __restrict__ bidx, int n_used,
                            float4* __restrict__ kc_out,
                            float4* __restrict__ vc_out, int nb_scat) {
    __shared__ __half th[64][132];

    const int bx = blockIdx.x;
    const int tid = threadIdx.x;

    if (bx < NB_COPY) {
        const int cb = bx >> 7;
        for (int t = 0; t < n_used; ++t)
            if (bidx[t] == cb) return;
        const size_t i = (size_t)cb * BLK_E4 + ((bx & 127) << 8) + tid;
        kc_out[i] = kc_in[i];
        vc_out[i] = vc_in[i];
    } else if (bx < NB_COPY + nb_scat) {
        const int bj = bx - NB_COPY;
        const int blk = bj >> 7;
        const int i = ((bj & 127) << 8) + tid;
        const size_t src = (size_t)blk * BLK_E4 + i;
        const size_t dst = (size_t)bidx[blk] * BLK_E4 + i;
        kc_out[dst] = k[src];
        vc_out[dst] = v[src];
    } else if (bx < NB_COPY + nb_scat + NB_CK) {
        const int rg = (bx - NB_COPY - nb_scat) * 4 + (tid >> 6);  // K row id
        const int p  = tid & 63;                                    // float2 pair
        const int b   = rg >> 13;
        const int hkv = (rg >> 10) & 7;
        const int s   = rg & (S - 1);
        const float2 kv = reinterpret_cast<const float2*>(
            k)[((size_t)(b * S + s) * HKV + hkv) * 64 + p];
        const uint32_t off = (uint32_t)((p >> 4) * 64 + (p & 3) * 16 +
                                        ((p >> 3) & 1) * 8 + ((p >> 2) & 1) * 4);
        uint32_t* o32 = reinterpret_cast<uint32_t*>(g_K);
        o32[((size_t)rg * 256 + off) >> 2] = pkh(kv.x, kv.y);
    } else {
        const int bj = bx - NB_COPY - nb_scat - NB_CK;
        const int bh = bj >> 4;   // b*HKV+hkv
        const int st = bj & 15;   // s-tile of 64
        const int b = bh >> 3, hkv = bh & 7;

#pragma unroll
        for (int it = 0; it < 8; ++it) {
            int c = it * 256 + tid;
            int s = c >> 5, d4 = c & 31;
            float4 vv = v[((size_t)(b * S + st * 64 + s) * HKV + hkv) * 32 + d4];
            th[s][4 * d4 + 0] = __float2half_rn(vv.x);
            th[s][4 * d4 + 1] = __float2half_rn(vv.y);
            th[s][4 * d4 + 2] = __float2half_rn(vv.z);
            th[s][4 * d4 + 3] = __float2half_rn(vv.w);
        }
        __syncthreads();

#pragma unroll
        for (int it = 0; it < 8; ++it) {
            int c = it * 256 + tid;
            int d = c >> 4, u = c & 15;
            int kk = u >> 2, lc = u & 3;
            int s0 = kk * 16 + 2 * lc;
            uint2 val;
            val.x = pkh(__half2float(th[s0][d]), __half2float(th[s0 + 1][d]));
            val.y = pkh(__half2float(th[s0 + 8][d]), __half2float(th[s0 + 9][d]));
            const uint32_t off = (uint32_t)((kk >> 1) * 64 + lc * 16 +
                                            (kk & 1) * 8);
            reinterpret_cast<uint2*>(
                g_V)[(((size_t)bh * D + d) * 2048 + st * 128 + off) >> 3] = val;
        }
    }
}

// ===========================================================================
// Flash attention. Grid (S/64, H, B), 128 threads (4 warps), 2 CTAs/SM.
// Explicit 2-stage LDS/MMA software pipelines; softmax halves interleaved
// with GEMM2 halves. Fixed-max exp2 softmax; l reduced once at epilogue.
// ===========================================================================
__global__ __launch_bounds__(128, 2) void attn_mma_kernel(
    const float* __restrict__ qg_, const float* __restrict__ alibi,
    float* __restrict__ out) {
    extern __shared__ char smem[];
    const uint32_t sb = s2u(smem);

    const int qt = (int)gridDim.x - 1 - (int)blockIdx.x;  // reversed order
    const int h  = blockIdx.y;
    const int b  = blockIdx.z;
    const int hkv = h >> 2;
    const int q0 = qt * BR;

    const int tid  = threadIdx.x;
    const int wid  = tid >> 5;
    const int lane = tid & 31;
    const int m0   = wid * 16;
    const int lr   = lane >> 2;
    const int lc   = lane & 3;

    const float slope2 = alibi[h] * LOG2E;
    const int rA = q0 + m0 + lr;
    const int rB = rA + 8;

    const char* kgl = reinterpret_cast<const char*>(g_K) +
                      (size_t)(b * HKV + hkv) * S * 256;
    const char* vgl = reinterpret_cast<const char*>(g_V) +
                      (size_t)(b * HKV + hkv) * D * 2048;

    // ---- prefetch tile 0 ----
#pragma unroll
    for (int it = 0; it < 8; ++it) {
        int c = it * 128 + tid;
        int kv = c >> 4, u = c & 15;
        cpa16(sb + BUF_K + kv * RS_K + u * 16, kgl + kv * 256 + u * 16);
    }
#pragma unroll
    for (int it = 0; it < 8; ++it) {
        int c = it * 128 + tid;
        int d = c >> 3, u = c & 7;
        cpa16(sb + BUF_V + d * RS_V + u * 16, vgl + (size_t)d * 2048 + u * 16);
    }
    CP_COMMIT();

    // ---- Q fragments: fp16 (SCALE2 folded) ----
    uint32_t qh[8][4];
    {
        const float2* q2 = reinterpret_cast<const float2*>(qg_);
        const size_t baseA = ((size_t)(b * S + rA) * H + h) * 64;
        const size_t baseB = baseA + (size_t)8 * H * 64;
#pragma unroll
        for (int ks = 0; ks < 8; ++ks) {
            float2 x0 = q2[baseA + ks * 8 + lc];
            float2 x1 = q2[baseB + ks * 8 + lc];
            float2 x2 = q2[baseA + ks * 8 + 4 + lc];
            float2 x3 = q2[baseB + ks * 8 + 4 + lc];
            qh[ks][0] = pkh(x0.x * SCALE2, x0.y * SCALE2);
            qh[ks][1] = pkh(x1.x * SCALE2, x1.y * SCALE2);
            qh[ks][2] = pkh(x2.x * SCALE2, x2.y * SCALE2);
            qh[ks][3] = pkh(x3.x * SCALE2, x3.y * SCALE2);
        }
    }

    float oc[16][4];
#pragma unroll
    for (int j = 0; j < 16; ++j)
#pragma unroll
        for (int q = 0; q < 4; ++q) oc[j][q] = 0.f;
    float lA = 0.f, lB = 0.f;   // per-thread partial row sums

    const int ntiles = qt + 1;
    for (int jt = 0; jt < ntiles; ++jt) {
        if (jt + 1 < ntiles) {
            const uint32_t bufn = sb + (uint32_t)((jt + 1) & 1) * BUF_SZ;
            const char* kn = kgl + (size_t)(jt + 1) * 64 * 256;
            const char* vn = vgl + (size_t)(jt + 1) * 128;
#pragma unroll
            for (int it = 0; it < 8; ++it) {
                int c = it * 128 + tid;
                int kv = c >> 4, u = c & 15;
                cpa16(bufn + BUF_K + kv * RS_K + u * 16, kn + kv * 256 + u * 16);
            }
#pragma unroll
            for (int it = 0; it < 8; ++it) {
                int c = it * 128 + tid;
                int d = c >> 3, u = c & 7;
                cpa16(bufn + BUF_V + d * RS_V + u * 16,
                      vn + (size_t)d * 2048 + u * 16);
            }
            CP_COMMIT();
            CP_WAIT(1);
        } else {
            CP_WAIT(0);
        }
        __syncthreads();

        const char* bbp = smem + (size_t)(jt & 1) * BUF_SZ;
        const char* kbuf = bbp + BUF_K + lr * RS_K + lc * 16;
        const char* vbuf = bbp + BUF_V + lr * RS_V + lc * 16;

        // ---- GEMM1: S = Qh.Kh, 2-stage pipeline (4 LDS / 8 MMA per step) ----
        float sc[8][4];
#pragma unroll
        for (int j = 0; j < 8; ++j)
#pragma unroll
            for (int q = 0; q < 4; ++q) sc[j][q] = 0.f;

        {
            uint4 f0[4], f1[4];
#pragma unroll
            for (int j = 0; j < 4; ++j)
                f0[j] = *reinterpret_cast<const uint4*>(kbuf + j * (8 * RS_K));
#pragma unroll
            for (int s = 0; s < 8; ++s) {
                const int m = s >> 1, g = (s & 1) * 4;
                if (s < 7) {
                    const int mn = (s + 1) >> 1, gn = ((s + 1) & 1) * 4;
#pragma unroll
                    for (int j = 0; j < 4; ++j)
                        f1[j] = *reinterpret_cast<const uint4*>(
                            kbuf + (gn + j) * (8 * RS_K) + mn * 64);
                }
#pragma unroll
                for (int j = 0; j < 4; ++j) {
                    mma16816(sc[g + j], qh[2 * m][0], qh[2 * m][1],
                             qh[2 * m][2], qh[2 * m][3], f0[j].x, f0[j].y);
                    mma16816(sc[g + j], qh[2 * m + 1][0], qh[2 * m + 1][1],
                             qh[2 * m + 1][2], qh[2 * m + 1][3], f0[j].z,
                             f0[j].w);
                }
#pragma unroll
                for (int j = 0; j < 4; ++j) f0[j] = f1[j];
            }
        }

        // ---- softmax + GEMM2, interleaved by halves ----
        const bool diag = (jt == qt);
#pragma unroll
        for (int half = 0; half < 2; ++half) {
            const int jb = half * 4;
            // softmax for j-blocks [jb, jb+4)
            if (!diag) {
#pragma unroll
                for (int j = jb; j < jb + 4; ++j) {
                    const int cb = jt * BC + 8 * j + 2 * lc;
                    sc[j][0] = exp2f(fmaf(slope2, (float)(cb - rA),     sc[j][0]));
                    sc[j][1] = exp2f(fmaf(slope2, (float)(cb + 1 - rA), sc[j][1]));
                    sc[j][2] = exp2f(fmaf(slope2, (float)(cb - rB),     sc[j][2]));
                    sc[j][3] = exp2f(fmaf(slope2, (float)(cb + 1 - rB), sc[j][3]));
                    lA += sc[j][0] + sc[j][1];
                    lB += sc[j][2] + sc[j][3];
                }
            } else {
#pragma unroll
                for (int j = jb; j < jb + 4; ++j) {
                    const int cb = jt * BC + 8 * j + 2 * lc;
                    sc[j][0] = (cb     <= rA) ? exp2f(fmaf(slope2, (float)(cb - rA),     sc[j][0])) : 0.f;
                    sc[j][1] = (cb + 1 <= rA) ? exp2f(fmaf(slope2, (float)(cb + 1 - rA), sc[j][1])) : 0.f;
                    sc[j][2] = (cb     <= rB) ? exp2f(fmaf(slope2, (float)(cb - rB),     sc[j][2])) : 0.f;
                    sc[j][3] = (cb + 1 <= rB) ? exp2f(fmaf(slope2, (float)(cb + 1 - rB), sc[j][3])) : 0.f;
                    lA += sc[j][0] + sc[j][1];
                    lB += sc[j][2] + sc[j][3];
                }
            }

            // pack P fragments for this half (k-chunks 2*half, 2*half+1)
            const uint32_t aE0 = pkh(sc[jb][0], sc[jb][1]);
            const uint32_t aE1 = pkh(sc[jb][2], sc[jb][3]);
            const uint32_t aE2 = pkh(sc[jb + 1][0], sc[jb + 1][1]);
            const uint32_t aE3 = pkh(sc[jb + 1][2], sc[jb + 1][3]);
            const uint32_t aO0 = pkh(sc[jb + 2][0], sc[jb + 2][1]);
            const uint32_t aO1 = pkh(sc[jb + 2][2], sc[jb + 2][3]);
            const uint32_t aO2 = pkh(sc[jb + 3][0], sc[jb + 3][1]);
            const uint32_t aO3 = pkh(sc[jb + 3][2], sc[jb + 3][3]);

            // GEMM2 for this k-chunk pair: 2-stage pipeline over 16 j outputs
            {
                uint4 v0[4], v1[4];
#pragma unroll
                for (int j = 0; j < 4; ++j)
                    v0[j] = *reinterpret_cast<const uint4*>(
                        vbuf + j * (8 * RS_V) + half * 64);
#pragma unroll
                for (int c = 0; c < 4; ++c) {
                    if (c < 3) {
#pragma unroll
                        for (int j = 0; j < 4; ++j)
                            v1[j] = *reinterpret_cast<const uint4*>(
                                vbuf + ((c + 1) * 4 + j) * (8 * RS_V) +
                                half * 64);
                    }
#pragma unroll
                    for (int j = 0; j < 4; ++j) {
                        const int jo = c * 4 + j;
                        mma16816(oc[jo], aE0, aE1, aE2, aE3, v0[j].x, v0[j].y);
                        mma16816(oc[jo], aO0, aO1, aO2, aO3, v0[j].z, v0[j].w);
                    }
#pragma unroll
                    for (int j = 0; j < 4; ++j) v0[j] = v1[j];
                }
            }
        }
        __syncthreads();
    }

    // ---- epilogue: one cross-lane l reduction, normalize, store ----
    lA += __shfl_xor_sync(0xffffffffu, lA, 1);
    lA += __shfl_xor_sync(0xffffffffu, lA, 2);
    lB += __shfl_xor_sync(0xffffffffu, lB, 1);
    lB += __shfl_xor_sync(0xffffffffu, lB, 2);
    const float invA = 1.0f / lA;
    const float invB = 1.0f / lB;
    float2* ogA = reinterpret_cast<float2*>(out + ((size_t)(b * S + rA) * H + h) * D);
    float2* ogB = reinterpret_cast<float2*>(out + ((size_t)(b * S + rB) * H + h) * D);
#pragma unroll
    for (int j = 0; j < 16; ++j) {
        const int c2 = (8 * j + 2 * lc) >> 1;
        ogA[c2] = make_float2(oc[j][0] * invA, oc[j][1] * invA);
        ogB[c2] = make_float2(oc[j][2] * invB, oc[j][3] * invB);
    }
}

// ===========================================================================
// kernel_launch
// ===========================================================================
extern "C" void kernel_launch(void* const* d_in, const int* in_sizes, int n_in,
                              void* d_out, int out_size) {
    const float* q      = (const float*)d_in[0];
    const float* k      = (const float*)d_in[1];
    const float* v      = (const float*)d_in[2];
    const float* kc_in  = (const float*)d_in[3];
    const float* vc_in  = (const float*)d_in[4];
    const int*   bidx   = (const int*)d_in[5];
    const float* slopes = (const float*)d_in[6];

    float* out = (float*)d_out;
    const size_t out_elems   = (size_t)B * S * H * D;
    const size_t cache_elems = (size_t)in_sizes[3];
    float* kc_out = out + out_elems;
    float* vc_out = kc_out + cache_elems;
    const int n_used = in_sizes[5];

    const int nb_scat = n_used * 128;
    prep_kernel<<<NB_COPY + nb_scat + NB_CK + NB_CV, 256>>>(
        (const float4*)k, (const float4*)v,
        (const float4*)kc_in, (const float4*)vc_in, bidx, n_used,
        (float4*)kc_out, (float4*)vc_out, nb_scat);

    cudaFuncSetAttribute(attn_mma_kernel,
                         cudaFuncAttributeMaxDynamicSharedMemorySize,
                         SMEM_ATTN);
    dim3 grid(S / BR, H, B);
    attn_mma_kernel<<<grid, 128, SMEM_ATTN>>>(q, slopes, out);
}

// round 16
// speedup vs baseline: 1.0564x; 1.0564x over previous
#include <cuda_runtime.h>
#include <cuda_fp16.h>
#include <cstdint>

// ===========================================================================
// Problem constants
// ===========================================================================
namespace {
constexpr int B   = 4;
constexpr int S   = 1024;
constexpr int H   = 32;
constexpr int HKV = 8;
constexpr int D   = 128;

constexpr int BLK_E4 = 128 * HKV * D / 4;  // float4 per cache block group
constexpr int NCACHE = 64;                 // total cache blocks

// SCALE * log2(e): softmax computed in base-2 domain
constexpr float SCALE2 = 0.08838834764831845f * 1.4426950408889634f;
constexpr float LOG2E  = 1.4426950408889634f;

constexpr int BR = 64;    // q rows per CTA (4 warps x 16)
constexpr int BC = 64;    // kv cols per tile

// smem tiles, paired-fragment layout (R13-proven): one 16B unit = B-fragments
// of two consecutive k-steps. Row strides == 64 mod 128 B: conflict-free.
// K: 64 rows x 256B data, stride 320B ; V: 128 rows x 128B data, stride 192B
constexpr uint32_t RS_K = 320;
constexpr uint32_t RS_V = 192;
constexpr uint32_t BUF_K = 0;
constexpr uint32_t BUF_V = 64 * RS_K;            // 20480
constexpr uint32_t BUF_SZ = BUF_V + 128 * RS_V;  // 45056
constexpr uint32_t SMEM_ATTN = 2 * BUF_SZ;       // 90112 (x2 CTAs = 176KB/SM)

// prep kernel job block ranges
constexpr int NB_COPY = NCACHE * 128;         // 8192 (copy, skip-overwritten)
constexpr int NB_CK   = (B * HKV * S) / 4;    // 8192 (4 K-rows per block)
constexpr int NB_CV   = B * HKV * (S / 64);   // 512

constexpr uint32_t ONES2 = 0x3C003C00u;       // half2(1.0, 1.0)
}  // namespace

// pre-converted fp16 scratch (8 MB each)
__device__ __align__(256) uint4 g_K[(size_t)B * HKV * S * 256 / 16];
__device__ __align__(256) uint4 g_V[(size_t)B * HKV * D * 2048 / 16];

// ===========================================================================
// helpers
// ===========================================================================
static __device__ __forceinline__ void mma16816(float* c, uint32_t a0,
                                                uint32_t a1, uint32_t a2,
                                                uint32_t a3, uint32_t b0,
                                                uint32_t b1) {
    asm volatile(
        "mma.sync.aligned.m16n8k16.row.col.f32.f16.f16.f32 "
        "{%0,%1,%2,%3}, {%4,%5,%6,%7}, {%8,%9}, {%0,%1,%2,%3};"
        : "+f"(c[0]), "+f"(c[1]), "+f"(c[2]), "+f"(c[3])
        : "r"(a0), "r"(a1), "r"(a2), "r"(a3), "r"(b0), "r"(b1));
}

static __device__ __forceinline__ uint32_t pkh(float x, float y) {
    __half2 t = __floats2half2_rn(x, y);
    return *reinterpret_cast<uint32_t*>(&t);
}

// packed fp16x2 exp2 (one MUFU op for two values)
static __device__ __forceinline__ uint32_t h2exp2_(uint32_t x) {
    uint32_t r;
    asm("ex2.approx.f16x2 %0, %1;" : "=r"(r) : "r"(x));
    return r;
}

static __device__ __forceinline__ uint32_t s2u(const void* p) {
    uint32_t a;
    asm("{ .reg .u64 t; cvta.to.shared.u64 t, %1; cvt.u32.u64 %0, t; }"
        : "=r"(a) : "l"(p));
    return a;
}

static __device__ __forceinline__ void cpa16(uint32_t dst, const void* src) {
    asm volatile("cp.async.cg.shared.global [%0], [%1], 16;"
                 :: "r"(dst), "l"(src));
}
#define CP_COMMIT() asm volatile("cp.async.commit_group;" ::: "memory")
#define CP_WAIT(n) asm volatile("cp.async.wait_group %0;" :: "n"(n) : "memory")

// ===========================================================================
// Fused prep kernel: copy (skip-overwritten) + scatter + convert K + convert V
// (identical to R13)
// ===========================================================================
__global__ void prep_kernel(const float4* __restrict__ k,
                            const float4* __restrict__ v,
                            const float4* __restrict__ kc_in,
                            const float4* __restrict__ vc_in,
                            const int* __restrict__ bidx, int n_used,
                            float4* __restrict__ kc_out,
                            float4* __restrict__ vc_out, int nb_scat) {
    __shared__ __half th[64][132];

    const int bx = blockIdx.x;
    const int tid = threadIdx.x;

    if (bx < NB_COPY) {
        const int cb = bx >> 7;
        for (int t = 0; t < n_used; ++t)
            if (bidx[t] == cb) return;
        const size_t i = (size_t)cb * BLK_E4 + ((bx & 127) << 8) + tid;
        kc_out[i] = kc_in[i];
        vc_out[i] = vc_in[i];
    } else if (bx < NB_COPY + nb_scat) {
        const int bj = bx - NB_COPY;
        const int blk = bj >> 7;
        const int i = ((bj & 127) << 8) + tid;
        const size_t src = (size_t)blk * BLK_E4 + i;
        const size_t dst = (size_t)bidx[blk] * BLK_E4 + i;
        kc_out[dst] = k[src];
        vc_out[dst] = v[src];
    } else if (bx < NB_COPY + nb_scat + NB_CK) {
        const int rg = (bx - NB_COPY - nb_scat) * 4 + (tid >> 6);  // K row id
        const int p  = tid & 63;                                    // float2 pair
        const int b   = rg >> 13;
        const int hkv = (rg >> 10) & 7;
        const int s   = rg & (S - 1);
        const float2 kv = reinterpret_cast<const float2*>(
            k)[((size_t)(b * S + s) * HKV + hkv) * 64 + p];
        const uint32_t off = (uint32_t)((p >> 4) * 64 + (p & 3) * 16 +
                                        ((p >> 3) & 1) * 8 + ((p >> 2) & 1) * 4);
        uint32_t* o32 = reinterpret_cast<uint32_t*>(g_K);
        o32[((size_t)rg * 256 + off) >> 2] = pkh(kv.x, kv.y);
    } else {
        const int bj = bx - NB_COPY - nb_scat - NB_CK;
        const int bh = bj >> 4;   // b*HKV+hkv
        const int st = bj & 15;   // s-tile of 64
        const int b = bh >> 3, hkv = bh & 7;

#pragma unroll
        for (int it = 0; it < 8; ++it) {
            int c = it * 256 + tid;
            int s = c >> 5, d4 = c & 31;
            float4 vv = v[((size_t)(b * S + st * 64 + s) * HKV + hkv) * 32 + d4];
            th[s][4 * d4 + 0] = __float2half_rn(vv.x);
            th[s][4 * d4 + 1] = __float2half_rn(vv.y);
            th[s][4 * d4 + 2] = __float2half_rn(vv.z);
            th[s][4 * d4 + 3] = __float2half_rn(vv.w);
        }
        __syncthreads();

#pragma unroll
        for (int it = 0; it < 8; ++it) {
            int c = it * 256 + tid;
            int d = c >> 4, u = c & 15;
            int kk = u >> 2, lc = u & 3;
            int s0 = kk * 16 + 2 * lc;
            uint2 val;
            val.x = pkh(__half2float(th[s0][d]), __half2float(th[s0 + 1][d]));
            val.y = pkh(__half2float(th[s0 + 8][d]), __half2float(th[s0 + 9][d]));
            const uint32_t off = (uint32_t)((kk >> 1) * 64 + lc * 16 +
                                            (kk & 1) * 8);
            reinterpret_cast<uint2*>(
                g_V)[(((size_t)bh * D + d) * 2048 + st * 128 + off) >> 3] = val;
        }
    }
}

// ===========================================================================
// Flash attention (R13 structure). Grid (S/64, H, B), 128 thr, 2 CTAs/SM.
// Softmax: bias in fp32 -> pack half2 -> ex2.approx.f16x2 (result IS the
// GEMM2 A-fragment). Row sums l computed by tensor core: P x ones MMA.
// ===========================================================================
__global__ __launch_bounds__(128, 2) void attn_mma_kernel(
    const float* __restrict__ qg_, const float* __restrict__ alibi,
    float* __restrict__ out) {
    extern __shared__ char smem[];
    const uint32_t sb = s2u(smem);

    const int qt = (int)gridDim.x - 1 - (int)blockIdx.x;  // reversed order
    const int h  = blockIdx.y;
    const int b  = blockIdx.z;
    const int hkv = h >> 2;
    const int q0 = qt * BR;

    const int tid  = threadIdx.x;
    const int wid  = tid >> 5;
    const int lane = tid & 31;
    const int m0   = wid * 16;
    const int lr   = lane >> 2;
    const int lc   = lane & 3;

    const float slope2 = alibi[h] * LOG2E;
    const int rA = q0 + m0 + lr;
    const int rB = rA + 8;

    const char* kgl = reinterpret_cast<const char*>(g_K) +
                      (size_t)(b * HKV + hkv) * S * 256;
    const char* vgl = reinterpret_cast<const char*>(g_V) +
                      (size_t)(b * HKV + hkv) * D * 2048;

    // ---- prefetch tile 0 ----
#pragma unroll
    for (int it = 0; it < 8; ++it) {
        int c = it * 128 + tid;
        int kv = c >> 4, u = c & 15;
        cpa16(sb + BUF_K + kv * RS_K + u * 16, kgl + kv * 256 + u * 16);
    }
#pragma unroll
    for (int it = 0; it < 8; ++it) {
        int c = it * 128 + tid;
        int d = c >> 3, u = c & 7;
        cpa16(sb + BUF_V + d * RS_V + u * 16, vgl + (size_t)d * 2048 + u * 16);
    }
    CP_COMMIT();

    // ---- Q fragments: fp16 (SCALE2 folded) ----
    uint32_t qh[8][4];
    {
        const float2* q2 = reinterpret_cast<const float2*>(qg_);
        const size_t baseA = ((size_t)(b * S + rA) * H + h) * 64;
        const size_t baseB = baseA + (size_t)8 * H * 64;
#pragma unroll
        for (int ks = 0; ks < 8; ++ks) {
            float2 x0 = q2[baseA + ks * 8 + lc];
            float2 x1 = q2[baseB + ks * 8 + lc];
            float2 x2 = q2[baseA + ks * 8 + 4 + lc];
            float2 x3 = q2[baseB + ks * 8 + 4 + lc];
            qh[ks][0] = pkh(x0.x * SCALE2, x0.y * SCALE2);
            qh[ks][1] = pkh(x1.x * SCALE2, x1.y * SCALE2);
            qh[ks][2] = pkh(x2.x * SCALE2, x2.y * SCALE2);
            qh[ks][3] = pkh(x3.x * SCALE2, x3.y * SCALE2);
        }
    }

    float oc[16][4];
#pragma unroll
    for (int j = 0; j < 16; ++j)
#pragma unroll
        for (int q = 0; q < 4; ++q) oc[j][q] = 0.f;
    float lacc[4] = {0.f, 0.f, 0.f, 0.f};  // tensor-core row sums of P

    const int ntiles = qt + 1;
    for (int jt = 0; jt < ntiles; ++jt) {
        if (jt + 1 < ntiles) {
            const uint32_t bufn = sb + (uint32_t)((jt + 1) & 1) * BUF_SZ;
            const char* kn = kgl + (size_t)(jt + 1) * 64 * 256;
            const char* vn = vgl + (size_t)(jt + 1) * 128;
#pragma unroll
            for (int it = 0; it < 8; ++it) {
                int c = it * 128 + tid;
                int kv = c >> 4, u = c & 15;
                cpa16(bufn + BUF_K + kv * RS_K + u * 16, kn + kv * 256 + u * 16);
            }
#pragma unroll
            for (int it = 0; it < 8; ++it) {
                int c = it * 128 + tid;
                int d = c >> 3, u = c & 7;
                cpa16(bufn + BUF_V + d * RS_V + u * 16,
                      vn + (size_t)d * 2048 + u * 16);
            }
            CP_COMMIT();
            CP_WAIT(1);
        } else {
            CP_WAIT(0);
        }
        __syncthreads();

        const char* bbp = smem + (size_t)(jt & 1) * BUF_SZ;
        const char* kbuf = bbp + BUF_K + lr * RS_K + lc * 16;
        const char* vbuf = bbp + BUF_V + lr * RS_V + lc * 16;

        // ---- GEMM1: S = Qh.Kh (R13 burst: 8 LDS.128 + 16 MMA per ks-pair) ----
        float sc[8][4];
#pragma unroll
        for (int j = 0; j < 8; ++j)
#pragma unroll
            for (int q = 0; q < 4; ++q) sc[j][q] = 0.f;

#pragma unroll
        for (int m = 0; m < 4; ++m) {
            uint4 kb[8];
#pragma unroll
            for (int j = 0; j < 8; ++j)
                kb[j] = *reinterpret_cast<const uint4*>(
                    kbuf + j * (8 * RS_K) + m * 64);
#pragma unroll
            for (int j = 0; j < 8; ++j) {
                mma16816(sc[j], qh[2 * m][0], qh[2 * m][1], qh[2 * m][2],
                         qh[2 * m][3], kb[j].x, kb[j].y);
                mma16816(sc[j], qh[2 * m + 1][0], qh[2 * m + 1][1],
                         qh[2 * m + 1][2], qh[2 * m + 1][3], kb[j].z, kb[j].w);
            }
        }

        // ---- bias (+ mask on diagonal) in fp32, then f16x2 exp2 ----
        // p[j][0] = exp2(half2(rowA pair)), p[j][1] = exp2(half2(rowB pair))
        uint32_t p[8][2];
        if (jt < qt) {
#pragma unroll
            for (int j = 0; j < 8; ++j) {
                const int cb = jt * BC + 8 * j + 2 * lc;
                const float v0 = fmaf(slope2, (float)(cb - rA),     sc[j][0]);
                const float v1 = fmaf(slope2, (float)(cb + 1 - rA), sc[j][1]);
                const float v2 = fmaf(slope2, (float)(cb - rB),     sc[j][2]);
                const float v3 = fmaf(slope2, (float)(cb + 1 - rB), sc[j][3]);
                p[j][0] = h2exp2_(pkh(v0, v1));
                p[j][1] = h2exp2_(pkh(v2, v3));
            }
        } else {
#pragma unroll
            for (int j = 0; j < 8; ++j) {
                const int cb = jt * BC + 8 * j + 2 * lc;
                const float v0 = (cb     <= rA) ? fmaf(slope2, (float)(cb - rA),     sc[j][0]) : -1e30f;
                const float v1 = (cb + 1 <= rA) ? fmaf(slope2, (float)(cb + 1 - rA), sc[j][1]) : -1e30f;
                const float v2 = (cb     <= rB) ? fmaf(slope2, (float)(cb - rB),     sc[j][2]) : -1e30f;
                const float v3 = (cb + 1 <= rB) ? fmaf(slope2, (float)(cb + 1 - rB), sc[j][3]) : -1e30f;
                p[j][0] = h2exp2_(pkh(v0, v1));
                p[j][1] = h2exp2_(pkh(v2, v3));
            }
        }

        // ---- l row-sums via tensor core: lacc += P . ones ----
#pragma unroll
        for (int c = 0; c < 4; ++c)
            mma16816(lacc, p[2 * c][0], p[2 * c][1], p[2 * c + 1][0],
                     p[2 * c + 1][1], ONES2, ONES2);

        // ---- GEMM2: O += P.Vh (R13 burst structure) ----
#pragma unroll
        for (int m = 0; m < 2; ++m) {
            const uint32_t aE0 = p[4 * m][0],     aE1 = p[4 * m][1];
            const uint32_t aE2 = p[4 * m + 1][0], aE3 = p[4 * m + 1][1];
            const uint32_t aO0 = p[4 * m + 2][0], aO1 = p[4 * m + 2][1];
            const uint32_t aO2 = p[4 * m + 3][0], aO3 = p[4 * m + 3][1];
#pragma unroll
            for (int jh = 0; jh < 2; ++jh) {
                uint4 vb[8];
#pragma unroll
                for (int j8 = 0; j8 < 8; ++j8)
                    vb[j8] = *reinterpret_cast<const uint4*>(
                        vbuf + (jh * 8 + j8) * (8 * RS_V) + m * 64);
#pragma unroll
                for (int j8 = 0; j8 < 8; ++j8) {
                    const int j = jh * 8 + j8;
                    mma16816(oc[j], aE0, aE1, aE2, aE3, vb[j8].x, vb[j8].y);
                    mma16816(oc[j], aO0, aO1, aO2, aO3, vb[j8].z, vb[j8].w);
                }
            }
        }
        __syncthreads();
    }

    // ---- epilogue: lacc holds exact row sums (all cols equal) ----
    const float invA = 1.0f / lacc[0];
    const float invB = 1.0f / lacc[2];
    float2* ogA = reinterpret_cast<float2*>(out + ((size_t)(b * S + rA) * H + h) * D);
    float2* ogB = reinterpret_cast<float2*>(out + ((size_t)(b * S + rB) * H + h) * D);
#pragma unroll
    for (int j = 0; j < 16; ++j) {
        const int c2 = (8 * j + 2 * lc) >> 1;
        ogA[c2] = make_float2(oc[j][0] * invA, oc[j][1] * invA);
        ogB[c2] = make_float2(oc[j][2] * invB, oc[j][3] * invB);
    }
}

// ===========================================================================
// kernel_launch
// ===========================================================================
extern "C" void kernel_launch(void* const* d_in, const int* in_sizes, int n_in,
                              void* d_out, int out_size) {
    const float* q      = (const float*)d_in[0];
    const float* k      = (const float*)d_in[1];
    const float* v      = (const float*)d_in[2];
    const float* kc_in  = (const float*)d_in[3];
    const float* vc_in  = (const float*)d_in[4];
    const int*   bidx   = (const int*)d_in[5];
    const float* slopes = (const float*)d_in[6];

    float* out = (float*)d_out;
    const size_t out_elems   = (size_t)B * S * H * D;
    const size_t cache_elems = (size_t)in_sizes[3];
    float* kc_out = out + out_elems;
    float* vc_out = kc_out + cache_elems;
    const int n_used = in_sizes[5];

    const int nb_scat = n_used * 128;
    prep_kernel<<<NB_COPY + nb_scat + NB_CK + NB_CV, 256>>>(
        (const float4*)k, (const float4*)v,
        (const float4*)kc_in, (const float4*)vc_in, bidx, n_used,
        (float4*)kc_out, (float4*)vc_out, nb_scat);

    cudaFuncSetAttribute(attn_mma_kernel,
                         cudaFuncAttributeMaxDynamicSharedMemorySize,
                         SMEM_ATTN);
    dim3 grid(S / BR, H, B);
    attn_mma_kernel<<<grid, 128, SMEM_ATTN>>>(q, slopes, out);
}